// round 8
// baseline (speedup 1.0000x reference)
#include <cuda_runtime.h>
#include <cuda_bf16.h>
#include <cstdint>

// Problem shapes (fixed by the dataset's setup_inputs)
constexpr int B = 16;
constexpr int S = 512;
constexpr int D = 768;     // span_dim
constexpr int E = 128;     // distance embedding dim
constexpr int T = 64;
constexpr int O = 64;
constexpr int P = T * O;            // 4096 pairs per batch
constexpr int OUT_D = 2 * D + E;    // 1664 floats per output row
constexpr int D4 = D / 4;           // 192 float4
constexpr int E4 = E / 4;           // 32 float4
constexpr int OUT_D4 = OUT_D / 4;   // 416 float4
constexpr int NBINS = 14;

constexpr int TT = 4;               // targets per block
constexpr int TO = 4;               // opinions per block
constexpr int NROWS = TT * TO;      // 16 output rows per block
constexpr int NSPAN = TT + TO;      // 8 unique span rows staged in smem
constexpr int THREADS = OUT_D4;     // 416 = one thread per output column float4

// bucket = (# bins <= width) - 1; bins[0]=0 and width>=0,
// so bucket = sum_{i=1..13} (width >= bins[i]).
__constant__ int c_bins[NBINS] = {0, 1, 2, 3, 4, 5, 7, 8, 15, 16, 31, 32, 63, 64};

__device__ __forceinline__ int bucketize(int w) {
    int bucket = 0;
#pragma unroll
    for (int i = 1; i < NBINS; ++i)
        bucket += (w >= c_bins[i]) ? 1 : 0;
    return bucket;
}

// One block = 4x4 (target x opinion) tile = 16 output rows.
// The 8 unique span rows (24 KB) are loaded from global ONCE into smem,
// then 416 threads (one per output float4 column) write all 16 rows.
// Section boundaries (192, 384) are multiples of 32 -> warp-uniform branches.
__global__ __launch_bounds__(THREADS, 4)
void pair_rep_kernel(const float4* __restrict__ spans,      // [B,S,D/4]
                     const float4* __restrict__ dist_emb,   // [14,E/4]
                     const int2*   __restrict__ span_idx,   // [S]
                     const int*    __restrict__ tgt,        // [B,T]
                     const int*    __restrict__ opi,        // [B,O]
                     float4*       __restrict__ out)        // [B*P, OUT_D/4]
{
    __shared__ float4 s_span[NSPAN * D4];   // 8 * 192 * 16B = 24576 B
    __shared__ int    s_sidx[NSPAN];
    __shared__ int    s_doff[NROWS];

    const int tid = threadIdx.x;            // 0..415
    const int blk = blockIdx.x;             // 0 .. B*(T/4)*(O/4)-1 = 4095
    const int b   = blk >> 8;               // / 256
    const int r   = blk & 255;
    const int t0  = (r >> 4) * TT;          // target tile base
    const int o0  = (r & 15) * TO;          // opinion tile base

    // Stage A: fetch the 8 span indices
    if (tid < NSPAN) {
        s_sidx[tid] = (tid < TT) ? __ldg(&tgt[b * T + t0 + tid])
                                 : __ldg(&opi[b * O + o0 + (tid - TT)]);
    }
    __syncthreads();

    // Stage B: load 8 span rows (1536 float4) into smem + compute 16 buckets
    const float4* spb = spans + (size_t)b * S * D4;
#pragma unroll
    for (int j = tid; j < NSPAN * D4; j += THREADS) {
        const int row = j / D4;
        const int col = j - row * D4;
        s_span[j] = __ldg(&spb[(size_t)s_sidx[row] * D4 + col]);
    }
    if (tid < NROWS) {
        const int trow = tid >> 2;
        const int ocol = tid & 3;
        const int2 ab = __ldg(&span_idx[s_sidx[trow]]);
        const int2 cd = __ldg(&span_idx[s_sidx[TT + ocol]]);
        const int w = min(abs(ab.y - cd.x), abs(ab.x - cd.y));
        s_doff[tid] = bucketize(w) * E4;
    }
    __syncthreads();

    // Stage C: write 16 output rows. Thread tid owns output column tid.
    const int col = tid;
    float4* base = out + ((size_t)b * P + (size_t)t0 * O + o0) * OUT_D4 + col;

#pragma unroll
    for (int row = 0; row < NROWS; ++row) {
        const int trow = row >> 2;
        const int ocol = row & 3;
        float4 v;
        if (col < D4) {
            v = s_span[trow * D4 + col];                       // span_t section
        } else if (col < 2 * D4) {
            v = s_span[(TT + ocol) * D4 + (col - D4)];         // span_o section
        } else {
            v = __ldg(&dist_emb[s_doff[row] + (col - 2 * D4)]); // dist section (L1-hot)
        }
        __stcs(base + ((size_t)trow * O + ocol) * OUT_D4, v);
    }
}

extern "C" void kernel_launch(void* const* d_in, const int* in_sizes, int n_in,
                              void* d_out, int out_size)
{
    // metadata order: spans, dist_emb, span_indices, target_indices, opinion_indices
    const float4* spans    = (const float4*)d_in[0];
    const float4* dist_emb = (const float4*)d_in[1];
    const int2*   span_idx = (const int2*)  d_in[2];
    const int*    tgt      = (const int*)   d_in[3];
    const int*    opi      = (const int*)   d_in[4];
    float4*       out      = (float4*)d_out;

    dim3 grid(B * (T / TT) * (O / TO));   // 4096 blocks, 16 rows each
    dim3 block(THREADS);                  // 416 threads = 13 warps
    pair_rep_kernel<<<grid, block>>>(spans, dist_emb, span_idx, tgt, opi, out);
}

// round 9
// speedup vs baseline: 1.1084x; 1.1084x over previous
#include <cuda_runtime.h>
#include <cuda_bf16.h>
#include <cstdint>

// Problem shapes (fixed by the dataset's setup_inputs)
constexpr int B = 16;
constexpr int S = 512;
constexpr int D = 768;     // span_dim
constexpr int E = 128;     // distance embedding dim
constexpr int T = 64;
constexpr int O = 64;
constexpr int P = T * O;            // 4096 pairs per batch
constexpr int OUT_D = 2 * D + E;    // 1664 floats per output row
constexpr int D4 = D / 4;           // 192 float4
constexpr int E4 = E / 4;           // 32 float4
constexpr int OUT_D4 = OUT_D / 4;   // 416 float4
constexpr int NBINS = 14;

constexpr int TT = 4;               // targets per block
constexpr int TO = 4;               // opinions per block
constexpr int THREADS = OUT_D4;     // 416 threads = 13 warps, one per out column

// bucket = (# bins <= width) - 1; bins[0]=0 and width>=0,
// so bucket = sum_{i=1..13} (width >= bins[i]).
__constant__ int c_bins[NBINS] = {0, 1, 2, 3, 4, 5, 7, 8, 15, 16, 31, 32, 63, 64};

__device__ __forceinline__ int bucketize(int w) {
    int bucket = 0;
#pragma unroll
    for (int i = 1; i < NBINS; ++i)
        bucket += (w >= c_bins[i]) ? 1 : 0;
    return bucket;
}

// One block = 4x4 (target x opinion) tile = 16 output rows, NO smem, NO sync.
// Thread tid owns output column tid for all 16 rows:
//   warps 0-5  (tid   0..191): hold the 4 target float4s in regs, store 16x
//   warps 6-11 (tid 192..383): hold the 4 opinion float4s in regs, store 16x
//   warp  12   (tid 384..415): buckets + dist sections (dist_emb is L1-hot)
// Span global reads: 24 KB/block (each unique value read once) vs 72 KB in R4.
__global__ __launch_bounds__(THREADS, 4)
void pair_rep_kernel(const float4* __restrict__ spans,      // [B,S,D/4]
                     const float4* __restrict__ dist_emb,   // [14,E/4]
                     const int2*   __restrict__ span_idx,   // [S]
                     const int*    __restrict__ tgt,        // [B,T]
                     const int*    __restrict__ opi,        // [B,O]
                     float4*       __restrict__ out)        // [B*P, OUT_D/4]
{
    const int tid = threadIdx.x;            // 0..415
    const int blk = blockIdx.x;             // 0 .. B*(T/4)*(O/4)-1 = 4095
    const int b   = blk >> 8;               // / 256
    const int r   = blk & 255;
    const int t0  = (r >> 4) * TT;
    const int o0  = (r & 15) * TO;

    const float4* spb = spans + (size_t)b * S * D4;
    // base already includes this thread's column offset
    float4* base = out + ((size_t)b * P + (size_t)t0 * O + o0) * OUT_D4 + tid;

    if (tid < D4) {
        // ---- span_t warps: 4 loads, each stored to 4 rows ----
        float4 v[TT];
#pragma unroll
        for (int i = 0; i < TT; ++i) {
            const int ti = __ldg(&tgt[b * T + t0 + i]);
            v[i] = __ldg(&spb[(size_t)ti * D4 + tid]);
        }
#pragma unroll
        for (int trow = 0; trow < TT; ++trow)
#pragma unroll
            for (int oc = 0; oc < TO; ++oc)
                __stcs(base + ((size_t)trow * O + oc) * OUT_D4, v[trow]);
    } else if (tid < 2 * D4) {
        // ---- span_o warps: 4 loads, each stored to 4 rows ----
        const int c = tid - D4;
        float4 v[TO];
#pragma unroll
        for (int i = 0; i < TO; ++i) {
            const int oi = __ldg(&opi[b * O + o0 + i]);
            v[i] = __ldg(&spb[(size_t)oi * D4 + c]);
        }
#pragma unroll
        for (int trow = 0; trow < TT; ++trow)
#pragma unroll
            for (int oc = 0; oc < TO; ++oc)
                __stcs(base + ((size_t)trow * O + oc) * OUT_D4, v[oc]);
    } else {
        // ---- dist warp: 16 buckets computed locally, 16 L1-hot loads ----
        const int c = tid - 2 * D4;          // 0..31
        int2 ab[TT], cd[TO];
#pragma unroll
        for (int i = 0; i < TT; ++i)
            ab[i] = __ldg(&span_idx[__ldg(&tgt[b * T + t0 + i])]);
#pragma unroll
        for (int i = 0; i < TO; ++i)
            cd[i] = __ldg(&span_idx[__ldg(&opi[b * O + o0 + i])]);

#pragma unroll
        for (int trow = 0; trow < TT; ++trow) {
            // batch of 4: 4 independent loads in flight, then 4 stores
            float4 vd[TO];
#pragma unroll
            for (int oc = 0; oc < TO; ++oc) {
                const int w = min(abs(ab[trow].y - cd[oc].x),
                                  abs(ab[trow].x - cd[oc].y));
                vd[oc] = __ldg(&dist_emb[(size_t)bucketize(w) * E4 + c]);
            }
#pragma unroll
            for (int oc = 0; oc < TO; ++oc)
                __stcs(base + ((size_t)trow * O + oc) * OUT_D4, vd[oc]);
        }
    }
}

extern "C" void kernel_launch(void* const* d_in, const int* in_sizes, int n_in,
                              void* d_out, int out_size)
{
    // metadata order: spans, dist_emb, span_indices, target_indices, opinion_indices
    const float4* spans    = (const float4*)d_in[0];
    const float4* dist_emb = (const float4*)d_in[1];
    const int2*   span_idx = (const int2*)  d_in[2];
    const int*    tgt      = (const int*)   d_in[3];
    const int*    opi      = (const int*)   d_in[4];
    float4*       out      = (float4*)d_out;

    dim3 grid(B * (T / TT) * (O / TO));   // 4096 blocks, 16 rows each
    dim3 block(THREADS);                  // 416 threads, 13 warps
    pair_rep_kernel<<<grid, block>>>(spans, dist_emb, span_idx, tgt, opi, out);
}

// round 10
// speedup vs baseline: 1.1523x; 1.0396x over previous
#include <cuda_runtime.h>
#include <cuda_bf16.h>
#include <cstdint>

// Problem shapes (fixed by the dataset's setup_inputs)
constexpr int B = 16;
constexpr int S = 512;
constexpr int D = 768;     // span_dim
constexpr int E = 128;     // distance embedding dim
constexpr int T = 64;
constexpr int O = 64;
constexpr int P = T * O;            // 4096 pairs per batch
constexpr int OUT_D = 2 * D + E;    // 1664 floats per output row
constexpr int D4 = D / 4;           // 192 float4
constexpr int E4 = E / 4;           // 32 float4
constexpr int OUT_D4 = OUT_D / 4;   // 416 float4
constexpr int NBINS = 14;

// bucket = (# bins <= width) - 1; bins[0]=0 and width>=0,
// so bucket = sum_{i=1..13} (width >= bins[i]).
__constant__ int c_bins[NBINS] = {0, 1, 2, 3, 4, 5, 7, 8, 15, 16, 31, 32, 63, 64};

__device__ __forceinline__ int bucketize(int w) {
    int bucket = 0;
#pragma unroll
    for (int i = 1; i < NBINS; ++i)
        bucket += (w >= c_bins[i]) ? 1 : 0;
    return bucket;
}

// R4 geometry (2 rows/block: same target, adjacent opinions; 32768 blocks)
// rebuilt with 256-thread blocks so 8 blocks/SM = 64/64 warps (100% theor. occ).
// The 832 output float4s of the 2 rows are covered in two warp-uniform phases:
//   phase 1, col = tid        (0..255):  cols 0..191 span_t | 192..255 span_o
//   phase 2, col = tid + 256  (tid<160): cols 256..383 span_o | 384..415 dist
// All branch boundaries (tid = 128, 160, 192) are warp-aligned.
__global__ __launch_bounds__(256, 8)
void pair_rep_kernel(const float4* __restrict__ spans,      // [B,S,D/4]
                     const float4* __restrict__ dist_emb,   // [14,E/4]
                     const int2*   __restrict__ span_idx,   // [S]
                     const int*    __restrict__ tgt,        // [B,T]
                     const int*    __restrict__ opi,        // [B,O]
                     float4*       __restrict__ out)        // [B*P, OUT_D/4]
{
    const int blk = blockIdx.x;            // 0 .. B*T*(O/2)-1 = 32767
    const int b   = blk >> 11;             // / 2048
    const int r   = blk & 2047;
    const int t   = r >> 5;                // / 32
    const int g   = r & 31;                // opinion pair group
    const int o0  = 2 * g;

    const int ti  = __ldg(&tgt[b * T + t]);
    const int oiA = __ldg(&opi[b * O + o0]);
    const int oiB = __ldg(&opi[b * O + o0 + 1]);

    const int tid = threadIdx.x;           // 0..255
    const float4* spb = spans + (size_t)b * S * D4;

    float4* dst0 = out + ((size_t)b * P + (size_t)t * O + o0) * OUT_D4;
    float4* dst1 = dst0 + OUT_D4;

    if (tid < D4) {
        // warps 0-5: phase 1 = span_t column tid (shared by both rows)
        const float4 vt = __ldg(&spb[(size_t)ti * D4 + tid]);

        if (tid < 128) {
            // warps 0-3: phase 2 = span_o column c2 = tid + 64
            const int c2 = tid + 64;
            const float4 voA = __ldg(&spb[(size_t)oiA * D4 + c2]);
            const float4 voB = __ldg(&spb[(size_t)oiB * D4 + c2]);
            __stcs(&dst0[tid], vt);
            __stcs(&dst1[tid], vt);
            __stcs(&dst0[D4 + c2], voA);
            __stcs(&dst1[D4 + c2], voB);
        } else if (tid < 160) {
            // warp 4: phase 2 = dist column d = tid - 128
            const int d = tid - 128;
            const int2 ab = __ldg(&span_idx[ti]);
            const int2 cdA = __ldg(&span_idx[oiA]);
            const int2 cdB = __ldg(&span_idx[oiB]);
            const int bkA = bucketize(min(abs(ab.y - cdA.x), abs(ab.x - cdA.y)));
            const int bkB = bucketize(min(abs(ab.y - cdB.x), abs(ab.x - cdB.y)));
            const float4 vdA = __ldg(&dist_emb[(size_t)bkA * E4 + d]);
            const float4 vdB = __ldg(&dist_emb[(size_t)bkB * E4 + d]);
            __stcs(&dst0[tid], vt);
            __stcs(&dst1[tid], vt);
            __stcs(&dst0[2 * D4 + d], vdA);
            __stcs(&dst1[2 * D4 + d], vdB);
        } else {
            // warp 5: span_t only
            __stcs(&dst0[tid], vt);
            __stcs(&dst1[tid], vt);
        }
    } else {
        // warps 6-7: phase 1 = span_o column c = tid - 192 (0..63)
        const int c = tid - D4;
        const float4 voA = __ldg(&spb[(size_t)oiA * D4 + c]);
        const float4 voB = __ldg(&spb[(size_t)oiB * D4 + c]);
        __stcs(&dst0[D4 + c], voA);
        __stcs(&dst1[D4 + c], voB);
    }
}

extern "C" void kernel_launch(void* const* d_in, const int* in_sizes, int n_in,
                              void* d_out, int out_size)
{
    // metadata order: spans, dist_emb, span_indices, target_indices, opinion_indices
    const float4* spans    = (const float4*)d_in[0];
    const float4* dist_emb = (const float4*)d_in[1];
    const int2*   span_idx = (const int2*)  d_in[2];
    const int*    tgt      = (const int*)   d_in[3];
    const int*    opi      = (const int*)   d_in[4];
    float4*       out      = (float4*)d_out;

    dim3 grid(B * T * (O / 2));   // 32768 blocks, two rows each
    dim3 block(256);              // 8 warps -> 8 blocks/SM = 64/64 warps
    pair_rep_kernel<<<grid, block>>>(spans, dist_emb, span_idx, tgt, opi, out);
}